// round 3
// baseline (speedup 1.0000x reference)
#include <cuda_runtime.h>
#include <cstdint>
#include <cstddef>

#define IN_F  512
#define OUT_F 512
#define MAX_M 50000

#define BM 128
#define BN 64
#define BK 32
#define KPAD 36   // BK + 4 words padding -> conflict-free frag reads

// Scratch for support = input @ weight (102.4 MB). Referenced directly by
// symbol inside kernels — no runtime API calls in kernel_launch.
__device__ float g_support[(size_t)MAX_M * OUT_F];

__device__ __forceinline__ uint32_t f2tf(float f) {
    uint32_t r;
    asm("cvt.rna.tf32.f32 %0, %1;" : "=r"(r) : "f"(f));
    return r;
}

__device__ __forceinline__ void mma_tf32(float* c, const uint32_t* a, const uint32_t* b) {
    asm volatile(
        "mma.sync.aligned.m16n8k8.row.col.f32.tf32.tf32.f32 "
        "{%0,%1,%2,%3}, {%4,%5,%6,%7}, {%8,%9}, {%0,%1,%2,%3};"
        : "+f"(c[0]), "+f"(c[1]), "+f"(c[2]), "+f"(c[3])
        : "r"(a[0]), "r"(a[1]), "r"(a[2]), "r"(a[3]),
          "r"(b[0]), "r"(b[1]));
}

// ---------------------------------------------------------------------------
// GEMM: g_support[M, OUT_F] = A[M, IN_F] * B[IN_F, OUT_F], TF32 tensor cores.
// Block tile 128x64, BK=32. 8 warps in a 4(M) x 2(N) grid, warp tile 32x32.
// ---------------------------------------------------------------------------
__global__ __launch_bounds__(256) void gemm_tf32_kernel(
    const float* __restrict__ A, const float* __restrict__ B, int M)
{
    __shared__ uint32_t As[BM][KPAD];   // row-major [m][k]
    __shared__ uint32_t Bs[BN][KPAD];   // transposed [n][k]

    const int tid  = threadIdx.x;
    const int warp = tid >> 5;
    const int lane = tid & 31;
    const int wm   = warp >> 1;     // 0..3
    const int wn   = warp & 1;      // 0..1
    const int gid  = lane >> 2;     // 0..7
    const int tig  = lane & 3;      // 0..3

    const int rb = blockIdx.y * BM;
    const int cb = blockIdx.x * BN;

    float acc[2][4][4];
    #pragma unroll
    for (int mt = 0; mt < 2; mt++)
        #pragma unroll
        for (int nt = 0; nt < 4; nt++)
            #pragma unroll
            for (int i = 0; i < 4; i++)
                acc[mt][nt][i] = 0.0f;

    for (int k0 = 0; k0 < IN_F; k0 += BK) {
        // --- load A tile 128x32 (4 passes of float4 per thread) ---
        {
            const int r = tid >> 3;          // 0..31
            const int c = (tid & 7) << 2;    // 0,4,...,28
            #pragma unroll
            for (int p = 0; p < 4; p++) {
                const int rr  = r + p * 32;
                const int row = rb + rr;
                float4 v = make_float4(0.f, 0.f, 0.f, 0.f);
                if (row < M)
                    v = *(const float4*)(A + (size_t)row * IN_F + k0 + c);
                As[rr][c + 0] = f2tf(v.x);
                As[rr][c + 1] = f2tf(v.y);
                As[rr][c + 2] = f2tf(v.z);
                As[rr][c + 3] = f2tf(v.w);
            }
        }
        // --- load B tile 32x64, store transposed (2 passes of float4) ---
        {
            const int r = tid >> 4;          // 0..15
            const int c = (tid & 15) << 2;   // 0,4,...,60
            #pragma unroll
            for (int p = 0; p < 2; p++) {
                const int kr = r + p * 16;
                float4 v = *(const float4*)(B + (size_t)(k0 + kr) * OUT_F + cb + c);
                Bs[c + 0][kr] = f2tf(v.x);
                Bs[c + 1][kr] = f2tf(v.y);
                Bs[c + 2][kr] = f2tf(v.z);
                Bs[c + 3][kr] = f2tf(v.w);
            }
        }
        __syncthreads();

        #pragma unroll
        for (int ks = 0; ks < 4; ks++) {
            const int kk = ks * 8;
            uint32_t af[2][4], bf[4][2];
            #pragma unroll
            for (int mt = 0; mt < 2; mt++) {
                const int r0 = wm * 32 + mt * 16 + gid;
                af[mt][0] = As[r0    ][kk + tig    ];
                af[mt][1] = As[r0 + 8][kk + tig    ];
                af[mt][2] = As[r0    ][kk + tig + 4];
                af[mt][3] = As[r0 + 8][kk + tig + 4];
            }
            #pragma unroll
            for (int nt = 0; nt < 4; nt++) {
                const int n0 = wn * 32 + nt * 8 + gid;
                bf[nt][0] = Bs[n0][kk + tig    ];
                bf[nt][1] = Bs[n0][kk + tig + 4];
            }
            #pragma unroll
            for (int mt = 0; mt < 2; mt++)
                #pragma unroll
                for (int nt = 0; nt < 4; nt++)
                    mma_tf32(acc[mt][nt], af[mt], bf[nt]);
        }
        __syncthreads();
    }

    // --- epilogue: float2 stores into g_support, guarded for M tail ---
    #pragma unroll
    for (int mt = 0; mt < 2; mt++) {
        const int r0 = rb + wm * 32 + mt * 16 + gid;
        #pragma unroll
        for (int nt = 0; nt < 4; nt++) {
            const int c0 = cb + wn * 32 + nt * 8 + tig * 2;
            if (r0 < M)
                *(float2*)(g_support + (size_t)r0 * OUT_F + c0) =
                    make_float2(acc[mt][nt][0], acc[mt][nt][1]);
            if (r0 + 8 < M)
                *(float2*)(g_support + (size_t)(r0 + 8) * OUT_F + c0) =
                    make_float2(acc[mt][nt][2], acc[mt][nt][3]);
        }
    }
}

// ---------------------------------------------------------------------------
// Init output with bias (bias is broadcast along rows).
// ---------------------------------------------------------------------------
__global__ void init_out_kernel(float4* __restrict__ out,
                                const float* __restrict__ bias, int total4)
{
    const int i = blockIdx.x * blockDim.x + threadIdx.x;
    if (i < total4) {
        const int c = (i & (OUT_F / 4 - 1)) * 4;
        out[i] = *(const float4*)(bias + c);
    }
}

// ---------------------------------------------------------------------------
// Scatter: one warp per edge. out[row] += g_support[col] * val, red.v4.f32.
// ---------------------------------------------------------------------------
__global__ __launch_bounds__(256) void scatter_kernel(
    const float* __restrict__ edge_val,
    const int* __restrict__ edge_row,
    const int* __restrict__ edge_col,
    float* __restrict__ out, int E)
{
    const int w    = (blockIdx.x * blockDim.x + threadIdx.x) >> 5;
    const int lane = threadIdx.x & 31;
    if (w >= E) return;

    const int   row = __ldg(edge_row + w);
    const int   col = __ldg(edge_col + w);
    const float v   = __ldg(edge_val + w);

    const float4* s = (const float4*)(g_support + (size_t)col * OUT_F);
    float*        o = out + (size_t)row * OUT_F;

    #pragma unroll
    for (int i = 0; i < 4; i++) {
        float4 x = s[lane + i * 32];
        x.x *= v; x.y *= v; x.z *= v; x.w *= v;
        float* p = o + (size_t)(lane + i * 32) * 4;
        asm volatile("red.global.add.v4.f32 [%0], {%1,%2,%3,%4};"
                     :: "l"(p), "f"(x.x), "f"(x.y), "f"(x.z), "f"(x.w)
                     : "memory");
    }
}

// ---------------------------------------------------------------------------
extern "C" void kernel_launch(void* const* d_in, const int* in_sizes, int n_in,
                              void* d_out, int out_size)
{
    const float* input    = (const float*)d_in[0];
    const float* weight   = (const float*)d_in[1];
    const float* bias     = (const float*)d_in[2];
    const float* edge_val = (const float*)d_in[3];
    const int*   edge_row = (const int*)d_in[4];
    const int*   edge_col = (const int*)d_in[5];

    const int M = in_sizes[0] / IN_F;
    const int E = in_sizes[3];

    // 1) g_support = input @ weight (TF32 tensor cores)
    dim3 grid_gemm(OUT_F / BN, (M + BM - 1) / BM);
    gemm_tf32_kernel<<<grid_gemm, 256>>>(input, weight, M);

    // 2) out = bias (row-broadcast)
    const int total4 = M * (OUT_F / 4);
    init_out_kernel<<<(total4 + 255) / 256, 256>>>((float4*)d_out, bias, total4);

    // 3) out[edge_row] += g_support[edge_col] * edge_val
    const int blocks = (E * 32 + 255) / 256;
    scatter_kernel<<<blocks, 256>>>(edge_val, edge_row, edge_col,
                                    (float*)d_out, E);
}

// round 7
// speedup vs baseline: 1.3754x; 1.3754x over previous
#include <cuda_runtime.h>
#include <cstdint>
#include <cstddef>

#define IN_F  512
#define OUT_F 512
#define MAX_M 50000

#define BM 128
#define BN 64
#define BK 32
#define KPAD 36   // 32 + 4 words padding -> conflict-free frag reads, 16B-aligned rows

// ---------------------------------------------------------------------------
// Device scratch (static __device__ globals per harness rules)
// ---------------------------------------------------------------------------
__device__ float g_support[(size_t)MAX_M * OUT_F];  // X*W result
__device__ float g_a[(size_t)MAX_M * IN_F];         // tf32-rounded input
__device__ float g_wt[(size_t)OUT_F * IN_F];        // W^T, tf32-rounded

__device__ __forceinline__ uint32_t f2tf(float f) {
    uint32_t r;
    asm("cvt.rna.tf32.f32 %0, %1;" : "=r"(r) : "f"(f));
    return r;
}
__device__ __forceinline__ uint32_t smem_u32(const void* p) {
    uint32_t a;
    asm("{ .reg .u64 t; cvta.to.shared.u64 t, %1; cvt.u32.u64 %0, t; }"
        : "=r"(a) : "l"(p));
    return a;
}

__device__ __forceinline__ void mma_tf32(float* c, const uint32_t* a, const uint32_t* b) {
    asm volatile(
        "mma.sync.aligned.m16n8k8.row.col.f32.tf32.tf32.f32 "
        "{%0,%1,%2,%3}, {%4,%5,%6,%7}, {%8,%9}, {%0,%1,%2,%3};"
        : "+f"(c[0]), "+f"(c[1]), "+f"(c[2]), "+f"(c[3])
        : "r"(a[0]), "r"(a[1]), "r"(a[2]), "r"(a[3]),
          "r"(b[0]), "r"(b[1]));
}

// ---------------------------------------------------------------------------
// GEMM: g_support = g_a[M,512] @ g_wt^T.  Tile 128x64, BK=32, cp.async 2-deep.
// 8 warps 4(M)x2(N), warp tile 32x32: 2 m-tiles x 4 n-tiles, 4 k-steps.
// ---------------------------------------------------------------------------
#define A_WORDS (BM * KPAD)            // per buffer
#define B_WORDS (BN * KPAD)
#define DYN_SMEM ((2 * A_WORDS + 2 * B_WORDS) * 4)  // 55296 B

__global__ __launch_bounds__(256, 4) void gemm_pipe(int M)
{
    extern __shared__ uint32_t sm[];
    uint32_t* As = sm;                  // [2][BM][KPAD]
    uint32_t* Bs = sm + 2 * A_WORDS;    // [2][BN][KPAD]

    const int tid  = threadIdx.x;
    const int warp = tid >> 5;
    const int lane = tid & 31;
    const int wm   = warp >> 1;     // 0..3
    const int wn   = warp & 1;      // 0..1
    const int gid  = lane >> 2;     // 0..7
    const int tig  = lane & 3;      // 0..3

    const int rb = blockIdx.y * BM;
    const int cb = blockIdx.x * BN;

    float acc[2][4][4];
    #pragma unroll
    for (int mt = 0; mt < 2; mt++)
        #pragma unroll
        for (int nt = 0; nt < 4; nt++)
            #pragma unroll
            for (int i = 0; i < 4; i++)
                acc[mt][nt][i] = 0.0f;

    // async load of one K-chunk into buffer `buf`
    auto load_chunk = [&](int chunk, int buf) {
        // A: 128 rows x 32 k = 1024 float4, 4 per thread
        const uint32_t abase = smem_u32(As + buf * A_WORDS);
        #pragma unroll
        for (int p = 0; p < 4; p++) {
            const int i = tid + p * 256;
            const int row = i >> 3, c4 = i & 7;
            const int grow = rb + row;
            const int ok = (grow < M);
            const float* src = g_a + (size_t)(ok ? grow : 0) * IN_F + chunk * BK + c4 * 4;
            const uint32_t dst = abase + (row * KPAD + c4 * 4) * 4;
            const int sz = ok ? 16 : 0;
            asm volatile("cp.async.cg.shared.global [%0], [%1], 16, %2;"
                         :: "r"(dst), "l"(src), "r"(sz));
        }
        // B: 64 rows (n) x 32 k = 512 float4, 2 per thread
        const uint32_t bbase = smem_u32(Bs + buf * B_WORDS);
        #pragma unroll
        for (int p = 0; p < 2; p++) {
            const int i = tid + p * 256;
            const int row = i >> 3, c4 = i & 7;
            const float* src = g_wt + (size_t)(cb + row) * IN_F + chunk * BK + c4 * 4;
            const uint32_t dst = bbase + (row * KPAD + c4 * 4) * 4;
            asm volatile("cp.async.cg.shared.global [%0], [%1], 16, 16;"
                         :: "r"(dst), "l"(src));
        }
        asm volatile("cp.async.commit_group;" ::: "memory");
    };

    load_chunk(0, 0);

    const int NCH = IN_F / BK;   // 16
    for (int c = 0; c < NCH; c++) {
        const int buf = c & 1;
        if (c + 1 < NCH) load_chunk(c + 1, buf ^ 1);
        if (c + 1 < NCH)
            asm volatile("cp.async.wait_group 1;" ::: "memory");
        else
            asm volatile("cp.async.wait_group 0;" ::: "memory");
        __syncthreads();

        const uint32_t* Ab = As + buf * A_WORDS;
        const uint32_t* Bb = Bs + buf * B_WORDS;

        #pragma unroll
        for (int ks = 0; ks < 4; ks++) {
            const int kk = ks * 8;
            uint32_t af[2][4], bf[4][2];
            #pragma unroll
            for (int mt = 0; mt < 2; mt++) {
                const int r0 = wm * 32 + mt * 16 + gid;
                af[mt][0] = Ab[(r0    ) * KPAD + kk + tig    ];
                af[mt][1] = Ab[(r0 + 8) * KPAD + kk + tig    ];
                af[mt][2] = Ab[(r0    ) * KPAD + kk + tig + 4];
                af[mt][3] = Ab[(r0 + 8) * KPAD + kk + tig + 4];
            }
            #pragma unroll
            for (int nt = 0; nt < 4; nt++) {
                const int n0 = wn * 32 + nt * 8 + gid;
                bf[nt][0] = Bb[n0 * KPAD + kk + tig    ];
                bf[nt][1] = Bb[n0 * KPAD + kk + tig + 4];
            }
            #pragma unroll
            for (int mt = 0; mt < 2; mt++)
                #pragma unroll
                for (int nt = 0; nt < 4; nt++)
                    mma_tf32(acc[mt][nt], af[mt], bf[nt]);
        }
        __syncthreads();   // protect buf before it is refilled next iteration
    }

    // epilogue: float2 stores, guarded for M tail
    #pragma unroll
    for (int mt = 0; mt < 2; mt++) {
        const int r0 = rb + wm * 32 + mt * 16 + gid;
        #pragma unroll
        for (int nt = 0; nt < 4; nt++) {
            const int c0 = cb + wn * 32 + nt * 8 + tig * 2;
            if (r0 < M)
                *(float2*)(g_support + (size_t)r0 * OUT_F + c0) =
                    make_float2(acc[mt][nt][0], acc[mt][nt][1]);
            if (r0 + 8 < M)
                *(float2*)(g_support + (size_t)(r0 + 8) * OUT_F + c0) =
                    make_float2(acc[mt][nt][2], acc[mt][nt][3]);
        }
    }
}

// ---------------------------------------------------------------------------
// Pre-round A to tf32 (rna).
// ---------------------------------------------------------------------------
__global__ void convert_a_kernel(const float4* __restrict__ in, int n4)
{
    const int i = blockIdx.x * blockDim.x + threadIdx.x;
    if (i < n4) {
        float4 v = in[i];
        v.x = __uint_as_float(f2tf(v.x));
        v.y = __uint_as_float(f2tf(v.y));
        v.z = __uint_as_float(f2tf(v.z));
        v.w = __uint_as_float(f2tf(v.w));
        ((float4*)g_a)[i] = v;
    }
}

// ---------------------------------------------------------------------------
// W^T with tf32 rounding: g_wt[n][k] = round(W[k][n])
// ---------------------------------------------------------------------------
__global__ void transpose_w_kernel(const float* __restrict__ w)
{
    __shared__ float t[32][33];
    const int bx = blockIdx.x * 32;   // n base
    const int by = blockIdx.y * 32;   // k base
    for (int j = threadIdx.y; j < 32; j += 8)
        t[j][threadIdx.x] = w[(size_t)(by + j) * OUT_F + bx + threadIdx.x];
    __syncthreads();
    for (int j = threadIdx.y; j < 32; j += 8)
        g_wt[(size_t)(bx + j) * IN_F + by + threadIdx.x] =
            __uint_as_float(f2tf(t[threadIdx.x][j]));
}

// ---------------------------------------------------------------------------
// out = bias (row-broadcast)
// ---------------------------------------------------------------------------
__global__ void init_out_kernel(float4* __restrict__ out,
                                const float* __restrict__ bias, int total4)
{
    const int i = blockIdx.x * blockDim.x + threadIdx.x;
    if (i < total4) {
        const int c = (i & (OUT_F / 4 - 1)) * 4;
        out[i] = *(const float4*)(bias + c);
    }
}

// ---------------------------------------------------------------------------
// Scatter: one warp per edge. out[row] += g_support[col] * val, red.v4.f32.
// ---------------------------------------------------------------------------
__global__ __launch_bounds__(256) void scatter_kernel(
    const float* __restrict__ edge_val,
    const int* __restrict__ edge_row,
    const int* __restrict__ edge_col,
    float* __restrict__ out, int E)
{
    const int w    = (blockIdx.x * blockDim.x + threadIdx.x) >> 5;
    const int lane = threadIdx.x & 31;
    if (w >= E) return;

    const int   row = __ldg(edge_row + w);
    const int   col = __ldg(edge_col + w);
    const float v   = __ldg(edge_val + w);

    const float4* s = (const float4*)(g_support + (size_t)col * OUT_F);
    float*        o = out + (size_t)row * OUT_F;

    #pragma unroll
    for (int i = 0; i < 4; i++) {
        float4 x = s[lane + i * 32];
        x.x *= v; x.y *= v; x.z *= v; x.w *= v;
        float* p = o + (size_t)(lane + i * 32) * 4;
        asm volatile("red.global.add.v4.f32 [%0], {%1,%2,%3,%4};"
                     :: "l"(p), "f"(x.x), "f"(x.y), "f"(x.z), "f"(x.w)
                     : "memory");
    }
}

// ---------------------------------------------------------------------------
extern "C" void kernel_launch(void* const* d_in, const int* in_sizes, int n_in,
                              void* d_out, int out_size)
{
    const float* input    = (const float*)d_in[0];
    const float* weight   = (const float*)d_in[1];
    const float* bias     = (const float*)d_in[2];
    const float* edge_val = (const float*)d_in[3];
    const int*   edge_row = (const int*)d_in[4];
    const int*   edge_col = (const int*)d_in[5];

    const int M = in_sizes[0] / IN_F;
    const int E = in_sizes[3];

    // 0) prep: round A to tf32, build rounded W^T
    const int n4 = M * IN_F / 4;
    convert_a_kernel<<<(n4 + 255) / 256, 256>>>((const float4*)input, n4);
    transpose_w_kernel<<<dim3(OUT_F / 32, IN_F / 32), dim3(32, 8)>>>(weight);

    // 1) g_support = A @ W (mma.sync tf32, cp.async double-buffered)
    cudaFuncSetAttribute(gemm_pipe,
                         cudaFuncAttributeMaxDynamicSharedMemorySize, DYN_SMEM);
    dim3 grid_gemm(OUT_F / BN, (M + BM - 1) / BM);
    gemm_pipe<<<grid_gemm, 256, DYN_SMEM>>>(M);

    // 2) out = bias
    const int total4 = M * (OUT_F / 4);
    init_out_kernel<<<(total4 + 255) / 256, 256>>>((float4*)d_out, bias, total4);

    // 3) out[edge_row] += g_support[edge_col] * edge_val
    const int blocks = (E * 32 + 255) / 256;
    scatter_kernel<<<blocks, 256>>>(edge_val, edge_row, edge_col,
                                    (float*)d_out, E);
}